// round 1
// baseline (speedup 1.0000x reference)
#include <cuda_runtime.h>
#include <cuda_bf16.h>
#include <math.h>

// Problem constants
#define EMB   768
#define DHEAD 256
#define NB    8
#define NSEQ  2048
#define NH    3
#define MTOT  (NB * NSEQ)          // 16384
#define CONC  (NH * DHEAD)         // 768

// Scratch (static device allocations — allowed)
__device__ float g_Q[NB * NH * NSEQ * DHEAD];   // [b,h,n,d]
__device__ float g_K[NB * NH * NSEQ * DHEAD];
__device__ float g_V[NB * NH * NSEQ * DHEAD];
__device__ float g_O[MTOT * CONC];              // [b,n, h*256+d]

// ---------------------------------------------------------------------------
// GEMM 1: QKV projections.  z = mat*3 + h ; out[b,h,n,d] = x @ W[mat,h] + b
// Tiles: BM=64, BN=64, BK=16, 256 threads, 4x4 microtile.
// ---------------------------------------------------------------------------
__global__ __launch_bounds__(256) void gemm_qkv_kernel(
    const float* __restrict__ x,
    const float* __restrict__ Wq, const float* __restrict__ bq,
    const float* __restrict__ Wk, const float* __restrict__ bk,
    const float* __restrict__ Wv, const float* __restrict__ bv)
{
    const int z   = blockIdx.z;
    const int mat = z / 3;
    const int h   = z % 3;
    const float* W;  const float* bias;  float* out;
    if (mat == 0)      { W = Wq; bias = bq; out = g_Q; }
    else if (mat == 1) { W = Wk; bias = bk; out = g_K; }
    else               { W = Wv; bias = bv; out = g_V; }
    W    += h * EMB * DHEAD;
    bias += h * DHEAD;

    __shared__ __align__(16) float As[16][64];
    __shared__ __align__(16) float Bs[16][64];

    const int tid = threadIdx.x;
    const int m0 = blockIdx.y * 64;
    const int n0 = blockIdx.x * 64;

    const int arow = tid >> 2;          // 0..63
    const int acol = (tid & 3) * 4;     // 0,4,8,12
    const int brow = tid >> 4;          // 0..15
    const int bcol = (tid & 15) * 4;    // 0..60

    const int ty = tid >> 4;            // 0..15
    const int tx = tid & 15;            // 0..15

    float acc[4][4] = {};

    for (int k0 = 0; k0 < EMB; k0 += 16) {
        float4 av = *(const float4*)&x[(size_t)(m0 + arow) * EMB + k0 + acol];
        As[acol + 0][arow] = av.x;
        As[acol + 1][arow] = av.y;
        As[acol + 2][arow] = av.z;
        As[acol + 3][arow] = av.w;
        float4 bv4 = *(const float4*)&W[(size_t)(k0 + brow) * DHEAD + n0 + bcol];
        *(float4*)&Bs[brow][bcol] = bv4;
        __syncthreads();
        #pragma unroll
        for (int k = 0; k < 16; k++) {
            float4 a4 = *(const float4*)&As[k][ty << 2];
            float4 b4 = *(const float4*)&Bs[k][tx << 2];
            float av_[4] = {a4.x, a4.y, a4.z, a4.w};
            float bv_[4] = {b4.x, b4.y, b4.z, b4.w};
            #pragma unroll
            for (int i = 0; i < 4; i++)
                #pragma unroll
                for (int j = 0; j < 4; j++)
                    acc[i][j] += av_[i] * bv_[j];
        }
        __syncthreads();
    }

    float4 bb = *(const float4*)&bias[n0 + (tx << 2)];
    #pragma unroll
    for (int i = 0; i < 4; i++) {
        int m  = m0 + (ty << 2) + i;
        int bi = m >> 11;            // / 2048
        int n  = m & 2047;
        float* orow = out + ((size_t)(bi * 3 + h) * NSEQ + n) * DHEAD + n0 + (tx << 2);
        float4 r;
        r.x = acc[i][0] + bb.x;
        r.y = acc[i][1] + bb.y;
        r.z = acc[i][2] + bb.z;
        r.w = acc[i][3] + bb.w;
        *(float4*)orow = r;
    }
}

// ---------------------------------------------------------------------------
// Attention: one CTA per (b,h, 64-query tile). 256 threads: 4 threads per
// query row, each owning a 64-wide slice of D. Flash-style over 64-key tiles.
// Dynamic smem: K tile (64x256) + V tile (64x256) + S (64x64) = 147456 B.
// ---------------------------------------------------------------------------
__global__ __launch_bounds__(256) void attn_kernel()
{
    extern __shared__ __align__(16) float sm[];
    float* Ks = sm;               // 16384 floats
    float* Vs = sm + 16384;       // 16384 floats
    float* Ss = sm + 32768;       // 4096 floats

    const int p  = blockIdx.y;
    const int b  = p / 3;
    const int h  = p % 3;
    const int q0 = blockIdx.x * 64;
    const int t  = threadIdx.x;
    const int r     = t >> 2;       // local query row 0..63
    const int qd    = t & 3;        // quadrant of D
    const int dbase = qd * 64;
    const float scale = 0.0625f;    // 1/sqrt(256)

    const size_t headbase = (size_t)(b * NH + h) * NSEQ * DHEAD;

    // Load this thread's Q slice into registers
    float q[64];
    {
        const float4* Qp = (const float4*)(g_Q + headbase + (size_t)(q0 + r) * DHEAD + dbase);
        #pragma unroll
        for (int i = 0; i < 16; i++) {
            float4 v = Qp[i];
            q[4*i+0] = v.x; q[4*i+1] = v.y; q[4*i+2] = v.z; q[4*i+3] = v.w;
        }
    }

    float O[64];
    #pragma unroll
    for (int d = 0; d < 64; d++) O[d] = 0.f;
    float mrow = -INFINITY, lsum = 0.f;

    for (int kt = 0; kt < NSEQ / 64; kt++) {
        // Stage K and V tiles (contiguous 16384-float blocks)
        const float4* Kg = (const float4*)(g_K + headbase + (size_t)kt * 64 * DHEAD);
        const float4* Vg = (const float4*)(g_V + headbase + (size_t)kt * 64 * DHEAD);
        #pragma unroll
        for (int i = 0; i < 16; i++) {
            ((float4*)Ks)[t + i * 256] = Kg[t + i * 256];
            ((float4*)Vs)[t + i * 256] = Vg[t + i * 256];
        }
        __syncthreads();

        // S = Q K^T (each 4-lane group reduces a full 256-dot)
        for (int j = 0; j < 64; j++) {
            const float4* kr = (const float4*)&Ks[j * 256 + dbase];
            float partial = 0.f;
            #pragma unroll
            for (int i = 0; i < 16; i++) {
                float4 kk = kr[i];
                partial += q[4*i+0]*kk.x + q[4*i+1]*kk.y + q[4*i+2]*kk.z + q[4*i+3]*kk.w;
            }
            partial += __shfl_xor_sync(0xffffffffu, partial, 1);
            partial += __shfl_xor_sync(0xffffffffu, partial, 2);
            if (qd == 0) Ss[r * 64 + j] = partial * scale;
        }
        __syncthreads();

        // Online softmax + O accumulation
        float tm = -INFINITY;
        #pragma unroll 8
        for (int j = 0; j < 64; j++) tm = fmaxf(tm, Ss[r * 64 + j]);
        float newm = fmaxf(mrow, tm);
        float corr = __expf(mrow - newm);
        lsum *= corr;
        #pragma unroll
        for (int d = 0; d < 64; d++) O[d] *= corr;

        for (int j = 0; j < 64; j++) {
            float pc = __expf(Ss[r * 64 + j] - newm);
            lsum += pc;
            const float4* vr = (const float4*)&Vs[j * 256 + dbase];
            #pragma unroll
            for (int i = 0; i < 16; i++) {
                float4 vv = vr[i];
                O[4*i+0] += pc * vv.x;
                O[4*i+1] += pc * vv.y;
                O[4*i+2] += pc * vv.z;
                O[4*i+3] += pc * vv.w;
            }
        }
        mrow = newm;
        __syncthreads();
    }

    // Normalize + store in concat layout [b,n, h*256+d]
    float inv = 1.f / lsum;
    float4* Op = (float4*)(g_O + (size_t)(b * NSEQ + q0 + r) * CONC + h * DHEAD + dbase);
    #pragma unroll
    for (int i = 0; i < 16; i++) {
        float4 v;
        v.x = O[4*i+0] * inv; v.y = O[4*i+1] * inv;
        v.z = O[4*i+2] * inv; v.w = O[4*i+3] * inv;
        Op[i] = v;
    }
}

// ---------------------------------------------------------------------------
// GEMM 2: output projection.  d_out[16384,768] = g_O[16384,768] @ W0 + b0
// ---------------------------------------------------------------------------
__global__ __launch_bounds__(256) void gemm_out_kernel(
    const float* __restrict__ W0, const float* __restrict__ b0,
    float* __restrict__ out)
{
    __shared__ __align__(16) float As[16][64];
    __shared__ __align__(16) float Bs[16][64];

    const int tid = threadIdx.x;
    const int m0 = blockIdx.y * 64;
    const int n0 = blockIdx.x * 64;

    const int arow = tid >> 2;
    const int acol = (tid & 3) * 4;
    const int brow = tid >> 4;
    const int bcol = (tid & 15) * 4;
    const int ty = tid >> 4;
    const int tx = tid & 15;

    float acc[4][4] = {};

    for (int k0 = 0; k0 < CONC; k0 += 16) {
        float4 av = *(const float4*)&g_O[(size_t)(m0 + arow) * CONC + k0 + acol];
        As[acol + 0][arow] = av.x;
        As[acol + 1][arow] = av.y;
        As[acol + 2][arow] = av.z;
        As[acol + 3][arow] = av.w;
        float4 bv4 = *(const float4*)&W0[(size_t)(k0 + brow) * CONC + n0 + bcol];
        *(float4*)&Bs[brow][bcol] = bv4;
        __syncthreads();
        #pragma unroll
        for (int k = 0; k < 16; k++) {
            float4 a4 = *(const float4*)&As[k][ty << 2];
            float4 b4 = *(const float4*)&Bs[k][tx << 2];
            float av_[4] = {a4.x, a4.y, a4.z, a4.w};
            float bv_[4] = {b4.x, b4.y, b4.z, b4.w};
            #pragma unroll
            for (int i = 0; i < 4; i++)
                #pragma unroll
                for (int j = 0; j < 4; j++)
                    acc[i][j] += av_[i] * bv_[j];
        }
        __syncthreads();
    }

    float4 bb = *(const float4*)&b0[n0 + (tx << 2)];
    #pragma unroll
    for (int i = 0; i < 4; i++) {
        int m = m0 + (ty << 2) + i;
        float4 r;
        r.x = acc[i][0] + bb.x;
        r.y = acc[i][1] + bb.y;
        r.z = acc[i][2] + bb.z;
        r.w = acc[i][3] + bb.w;
        *(float4*)&out[(size_t)m * CONC + n0 + (tx << 2)] = r;
    }
}

// ---------------------------------------------------------------------------
extern "C" void kernel_launch(void* const* d_in, const int* in_sizes, int n_in,
                              void* d_out, int out_size)
{
    const float* x  = (const float*)d_in[0];
    const float* Wq = (const float*)d_in[1];
    const float* bq = (const float*)d_in[2];
    const float* Wk = (const float*)d_in[3];
    const float* bk = (const float*)d_in[4];
    const float* Wv = (const float*)d_in[5];
    const float* bv = (const float*)d_in[6];
    const float* W0 = (const float*)d_in[7];
    const float* b0 = (const float*)d_in[8];
    float* out = (float*)d_out;

    // QKV projections: grid z = {Q,K,V} x heads
    gemm_qkv_kernel<<<dim3(DHEAD / 64, MTOT / 64, 9), 256>>>(x, Wq, bq, Wk, bk, Wv, bv);

    // Attention (144 KB dynamic smem)
    const int smem_bytes = (16384 + 16384 + 4096) * sizeof(float);
    cudaFuncSetAttribute(attn_kernel, cudaFuncAttributeMaxDynamicSharedMemorySize, smem_bytes);
    attn_kernel<<<dim3(NSEQ / 64, NB * NH), 256, smem_bytes>>>();

    // Output projection
    gemm_out_kernel<<<dim3(CONC / 64, MTOT / 64), 256>>>(W0, b0, out);
}

// round 3
// speedup vs baseline: 14.6445x; 14.6445x over previous
#include <cuda_runtime.h>
#include <cuda_bf16.h>
#include <math.h>

// Problem constants
#define EMB   768
#define DHEAD 256
#define NB    8
#define NSEQ  2048
#define NH    3
#define MTOT  (NB * NSEQ)          // 16384
#define CONC  (NH * DHEAD)         // 768
#define SCALE 0.0625f              // 1/sqrt(256)

// Scratch
__device__ float g_Q[NB * NH * NSEQ * DHEAD];   // [b,h,n,d]
__device__ float g_K[NB * NH * NSEQ * DHEAD];
__device__ float g_V[NB * NH * NSEQ * DHEAD];
__device__ float g_O[MTOT * CONC];              // [b,n, h*256+d]

// ---------------------------------------------------------------------------
// tf32 helpers
// ---------------------------------------------------------------------------
__device__ __forceinline__ unsigned tf32(float x) {
    unsigned u;
    asm("cvt.rna.tf32.f32 %0, %1;" : "=r"(u) : "f"(x));
    return u;
}

__device__ __forceinline__ void mma_tf32(float* d, const unsigned* a, const unsigned* b) {
    asm volatile(
        "mma.sync.aligned.m16n8k8.row.col.f32.tf32.tf32.f32 "
        "{%0,%1,%2,%3},{%4,%5,%6,%7},{%8,%9},{%0,%1,%2,%3};"
        : "+f"(d[0]), "+f"(d[1]), "+f"(d[2]), "+f"(d[3])
        : "r"(a[0]), "r"(a[1]), "r"(a[2]), "r"(a[3]), "r"(b[0]), "r"(b[1]));
}

// ---------------------------------------------------------------------------
// Shared GEMM mainloop: C(128x128) += A(128xK) * B(Kx128), BK=16.
// 8 warps as 2(m) x 4(n); each warp 64x32 (4 m-tiles x 4 n-tiles m16n8k8).
// ---------------------------------------------------------------------------
#define AS_ST 20
#define BS_ST 136

__device__ __forceinline__ void gemm_mainloop(
    const float* __restrict__ A, int lda,
    const float* __restrict__ B, int ldb,
    int K, int m0, int n0,
    float acc[4][4][4],
    float As[128][AS_ST], float Bs[16][BS_ST])
{
    const int tid  = threadIdx.x;
    const int lane = tid & 31;
    const int wid  = tid >> 5;
    const int wm   = wid & 1;    // 64-row block
    const int wn   = wid >> 1;   // 32-col block

    for (int k0 = 0; k0 < K; k0 += 16) {
        #pragma unroll
        for (int i = 0; i < 2; i++) {           // A tile 128x16
            int f = tid + i * 256;              // 0..511 float4s
            int row = f >> 2;
            int c4  = (f & 3) << 2;
            float4 v = *(const float4*)&A[(size_t)(m0 + row) * lda + k0 + c4];
            As[row][c4 + 0] = v.x; As[row][c4 + 1] = v.y;
            As[row][c4 + 2] = v.z; As[row][c4 + 3] = v.w;
        }
        #pragma unroll
        for (int i = 0; i < 2; i++) {           // B tile 16x128
            int f = tid + i * 256;
            int row = f >> 5;
            int c4  = (f & 31) << 2;
            float4 v = *(const float4*)&B[(size_t)(k0 + row) * ldb + n0 + c4];
            *(float4*)&Bs[row][c4] = v;
        }
        __syncthreads();

        #pragma unroll
        for (int ks = 0; ks < 2; ks++) {
            unsigned af[4][4], bf[4][2];
            #pragma unroll
            for (int mt = 0; mt < 4; mt++) {
                int r = wm * 64 + mt * 16 + (lane >> 2);
                int c = ks * 8 + (lane & 3);
                af[mt][0] = tf32(As[r][c]);
                af[mt][1] = tf32(As[r + 8][c]);
                af[mt][2] = tf32(As[r][c + 4]);
                af[mt][3] = tf32(As[r + 8][c + 4]);
            }
            #pragma unroll
            for (int nt = 0; nt < 4; nt++) {
                int cc = wn * 32 + nt * 8 + (lane >> 2);
                int rr = ks * 8 + (lane & 3);
                bf[nt][0] = tf32(Bs[rr][cc]);
                bf[nt][1] = tf32(Bs[rr + 4][cc]);
            }
            #pragma unroll
            for (int mt = 0; mt < 4; mt++)
                #pragma unroll
                for (int nt = 0; nt < 4; nt++)
                    mma_tf32(acc[mt][nt], af[mt], bf[nt]);
        }
        __syncthreads();
    }
}

// ---------------------------------------------------------------------------
// GEMM 1: QKV projections. z = mat*3 + h
// ---------------------------------------------------------------------------
__global__ __launch_bounds__(256) void gemm_qkv_mma(
    const float* __restrict__ x,
    const float* __restrict__ Wq, const float* __restrict__ bq,
    const float* __restrict__ Wk, const float* __restrict__ bk,
    const float* __restrict__ Wv, const float* __restrict__ bv)
{
    __shared__ float As[128][AS_ST];
    __shared__ float Bs[16][BS_ST];

    const int z = blockIdx.z, mat = z / 3, h = z % 3;
    const float* W; const float* bias; float* out;
    if (mat == 0)      { W = Wq; bias = bq; out = g_Q; }
    else if (mat == 1) { W = Wk; bias = bk; out = g_K; }
    else               { W = Wv; bias = bv; out = g_V; }
    W    += (size_t)h * EMB * DHEAD;
    bias += h * DHEAD;

    const int m0 = blockIdx.y * 128;
    const int n0 = blockIdx.x * 128;

    float acc[4][4][4] = {};
    gemm_mainloop(x, EMB, W, DHEAD, EMB, m0, n0, acc, As, Bs);

    const int lane = threadIdx.x & 31, wid = threadIdx.x >> 5;
    const int wm = wid & 1, wn = wid >> 1;
    #pragma unroll
    for (int mt = 0; mt < 4; mt++) {
        int gr0 = m0 + wm * 64 + mt * 16 + (lane >> 2);
        int gr1 = gr0 + 8;
        int bi0 = gr0 >> 11, n0r = gr0 & 2047;
        int bi1 = gr1 >> 11, n1r = gr1 & 2047;
        float* p0 = out + ((size_t)(bi0 * 3 + h) * NSEQ + n0r) * DHEAD;
        float* p1 = out + ((size_t)(bi1 * 3 + h) * NSEQ + n1r) * DHEAD;
        #pragma unroll
        for (int nt = 0; nt < 4; nt++) {
            int c = n0 + wn * 32 + nt * 8 + ((lane & 3) << 1);
            float b0v = bias[c], b1v = bias[c + 1];
            *(float2*)&p0[c] = make_float2(acc[mt][nt][0] + b0v, acc[mt][nt][1] + b1v);
            *(float2*)&p1[c] = make_float2(acc[mt][nt][2] + b0v, acc[mt][nt][3] + b1v);
        }
    }
}

// ---------------------------------------------------------------------------
// GEMM 2: output projection d_out[16384,768] = g_O @ W0 + b0
// ---------------------------------------------------------------------------
__global__ __launch_bounds__(256) void gemm_out_mma(
    const float* __restrict__ W0, const float* __restrict__ b0,
    float* __restrict__ outp)
{
    __shared__ float As[128][AS_ST];
    __shared__ float Bs[16][BS_ST];

    const int m0 = blockIdx.y * 128;
    const int n0 = blockIdx.x * 128;

    float acc[4][4][4] = {};
    gemm_mainloop(g_O, CONC, W0, CONC, CONC, m0, n0, acc, As, Bs);

    const int lane = threadIdx.x & 31, wid = threadIdx.x >> 5;
    const int wm = wid & 1, wn = wid >> 1;
    #pragma unroll
    for (int mt = 0; mt < 4; mt++) {
        int gr0 = m0 + wm * 64 + mt * 16 + (lane >> 2);
        int gr1 = gr0 + 8;
        #pragma unroll
        for (int nt = 0; nt < 4; nt++) {
            int c = n0 + wn * 32 + nt * 8 + ((lane & 3) << 1);
            float bb0 = b0[c], bb1 = b0[c + 1];
            *(float2*)&outp[(size_t)gr0 * CONC + c] =
                make_float2(acc[mt][nt][0] + bb0, acc[mt][nt][1] + bb1);
            *(float2*)&outp[(size_t)gr1 * CONC + c] =
                make_float2(acc[mt][nt][2] + bb0, acc[mt][nt][3] + bb1);
        }
    }
}

// ---------------------------------------------------------------------------
// Flash attention with tf32 mma. CTA = (64 queries, one (b,h)).
// 8 warps: wm = wid&3 -> 16-query row group; wn = wid>>2 -> half of keys (QK)
// / half of D (PV).
// smem strides conflict-free for fragment gathers:
//   Qs,Ks: 260 (%32=4), Vs: 264 (%32=8), Ps: 68 (%32=4)
// ---------------------------------------------------------------------------
#define Q_ST 260
#define K_ST 260
#define V_ST 264
#define P_ST 68
#define Q_OFF 0
#define K_OFF (64 * Q_ST)
#define V_OFF (K_OFF + 64 * K_ST)
#define P_OFF (V_OFF + 64 * V_ST)
#define M_OFF (P_OFF + 64 * P_ST)
#define ATTN_SMEM_FLOATS (M_OFF + 3 * 64)

__global__ __launch_bounds__(256) void attn_mma_kernel()
{
    extern __shared__ float sm[];
    float (*Qs)[Q_ST] = (float(*)[Q_ST])(sm + Q_OFF);
    float (*Ks)[K_ST] = (float(*)[K_ST])(sm + K_OFF);
    float (*Vs)[V_ST] = (float(*)[V_ST])(sm + V_OFF);
    float (*Ps)[P_ST] = (float(*)[P_ST])(sm + P_OFF);
    float* rowM = sm + M_OFF;
    float* rowL = rowM + 64;
    float* rowC = rowL + 64;

    const int t = threadIdx.x, lane = t & 31, wid = t >> 5;
    const int wm = wid & 3;    // 16-row group
    const int wn = wid >> 2;   // 0..1
    const int p = blockIdx.y, b = p / 3, h = p % 3;
    const int q0 = blockIdx.x * 64;
    const size_t hb = (size_t)(b * 3 + h) * NSEQ * DHEAD;

    // Stage Q (64x256)
    {
        const float4* Qg = (const float4*)(g_Q + hb + (size_t)q0 * DHEAD);
        #pragma unroll
        for (int i = 0; i < 16; i++) {
            int f = t + i * 256;
            int row = f >> 6, c4 = (f & 63) << 2;
            *(float4*)&Qs[row][c4] = Qg[f];
        }
    }
    if (t < 64) { rowM[t] = -INFINITY; rowL[t] = 0.f; }

    float o[16][4];
    #pragma unroll
    for (int i = 0; i < 16; i++)
        { o[i][0] = 0.f; o[i][1] = 0.f; o[i][2] = 0.f; o[i][3] = 0.f; }

    __syncthreads();

    for (int kt = 0; kt < NSEQ / 64; kt++) {
        // Stage K,V tiles
        const float4* Kg = (const float4*)(g_K + hb + (size_t)kt * 64 * DHEAD);
        const float4* Vg = (const float4*)(g_V + hb + (size_t)kt * 64 * DHEAD);
        #pragma unroll
        for (int i = 0; i < 16; i++) {
            int f = t + i * 256;
            int row = f >> 6, c4 = (f & 63) << 2;
            *(float4*)&Ks[row][c4] = Kg[f];
            *(float4*)&Vs[row][c4] = Vg[f];
        }
        __syncthreads();

        // S = Q K^T : per warp m16 (wm), 32 keys (wn*32), k=256
        float s[4][4] = {};
        #pragma unroll
        for (int ks = 0; ks < 32; ks++) {
            unsigned af[4];
            int r = wm * 16 + (lane >> 2);
            int c = ks * 8 + (lane & 3);
            af[0] = tf32(Qs[r][c]);
            af[1] = tf32(Qs[r + 8][c]);
            af[2] = tf32(Qs[r][c + 4]);
            af[3] = tf32(Qs[r + 8][c + 4]);
            #pragma unroll
            for (int nt = 0; nt < 4; nt++) {
                int key = wn * 32 + nt * 8 + (lane >> 2);
                unsigned bf[2] = { tf32(Ks[key][c]), tf32(Ks[key][c + 4]) };
                mma_tf32(s[nt], af, bf);
            }
        }

        // Write scaled S to Ps
        {
            int r = wm * 16 + (lane >> 2);
            #pragma unroll
            for (int nt = 0; nt < 4; nt++) {
                int c = wn * 32 + nt * 8 + ((lane & 3) << 1);
                *(float2*)&Ps[r][c]     = make_float2(s[nt][0] * SCALE, s[nt][1] * SCALE);
                *(float2*)&Ps[r + 8][c] = make_float2(s[nt][2] * SCALE, s[nt][3] * SCALE);
            }
        }
        __syncthreads();

        // Online softmax row pass: 4 threads per row
        {
            int r = t >> 2, sub = t & 3;
            float* pr = &Ps[r][sub * 16];
            float tm = -INFINITY;
            #pragma unroll
            for (int j = 0; j < 16; j++) tm = fmaxf(tm, pr[j]);
            tm = fmaxf(tm, __shfl_xor_sync(0xffffffffu, tm, 1));
            tm = fmaxf(tm, __shfl_xor_sync(0xffffffffu, tm, 2));
            float mprev = rowM[r];
            float newm = fmaxf(mprev, tm);
            float corr = __expf(mprev - newm);
            float sum = 0.f;
            #pragma unroll
            for (int j = 0; j < 16; j++) {
                float pv = __expf(pr[j] - newm);
                pr[j] = pv;
                sum += pv;
            }
            sum += __shfl_xor_sync(0xffffffffu, sum, 1);
            sum += __shfl_xor_sync(0xffffffffu, sum, 2);
            if (sub == 0) {
                rowM[r] = newm;
                rowL[r] = rowL[r] * corr + sum;
                rowC[r] = corr;
            }
        }
        __syncthreads();

        // Rescale O
        {
            float c0 = rowC[wm * 16 + (lane >> 2)];
            float c1 = rowC[wm * 16 + (lane >> 2) + 8];
            #pragma unroll
            for (int nt = 0; nt < 16; nt++) {
                o[nt][0] *= c0; o[nt][1] *= c0;
                o[nt][2] *= c1; o[nt][3] *= c1;
            }
        }

        // O += P V : per warp m16 x 128 D-cols (wn half), k=64
        #pragma unroll
        for (int ks = 0; ks < 8; ks++) {
            unsigned af[4];
            int r = wm * 16 + (lane >> 2);
            int c = ks * 8 + (lane & 3);
            af[0] = tf32(Ps[r][c]);
            af[1] = tf32(Ps[r + 8][c]);
            af[2] = tf32(Ps[r][c + 4]);
            af[3] = tf32(Ps[r + 8][c + 4]);
            #pragma unroll
            for (int nt = 0; nt < 16; nt++) {
                int d = wn * 128 + nt * 8 + (lane >> 2);
                unsigned bf[2] = { tf32(Vs[c][d]), tf32(Vs[c + 4][d]) };
                mma_tf32(o[nt], af, bf);
            }
        }
        __syncthreads();
    }

    // Epilogue: normalize + store concat layout [b, n, h*256 + d]
    {
        int r0 = wm * 16 + (lane >> 2), r1 = r0 + 8;
        float inv0 = 1.f / rowL[r0];
        float inv1 = 1.f / rowL[r1];
        size_t obase = ((size_t)b * NSEQ + q0) * CONC + h * DHEAD;
        #pragma unroll
        for (int nt = 0; nt < 16; nt++) {
            int c = wn * 128 + nt * 8 + ((lane & 3) << 1);
            *(float2*)&g_O[obase + (size_t)r0 * CONC + c] =
                make_float2(o[nt][0] * inv0, o[nt][1] * inv0);
            *(float2*)&g_O[obase + (size_t)r1 * CONC + c] =
                make_float2(o[nt][2] * inv1, o[nt][3] * inv1);
        }
    }
}

// ---------------------------------------------------------------------------
extern "C" void kernel_launch(void* const* d_in, const int* in_sizes, int n_in,
                              void* d_out, int out_size)
{
    const float* x  = (const float*)d_in[0];
    const float* Wq = (const float*)d_in[1];
    const float* bq = (const float*)d_in[2];
    const float* Wk = (const float*)d_in[3];
    const float* bk = (const float*)d_in[4];
    const float* Wv = (const float*)d_in[5];
    const float* bv = (const float*)d_in[6];
    const float* W0 = (const float*)d_in[7];
    const float* b0 = (const float*)d_in[8];
    float* out = (float*)d_out;

    // One-time attribute setup (outside any capture concerns after first call)
    static bool attr_done = false;
    if (!attr_done) {
        cudaFuncSetAttribute(attn_mma_kernel,
                             cudaFuncAttributeMaxDynamicSharedMemorySize,
                             ATTN_SMEM_FLOATS * (int)sizeof(float));
        attr_done = true;
    }

    gemm_qkv_mma<<<dim3(DHEAD / 128, MTOT / 128, 9), 256>>>(x, Wq, bq, Wk, bk, Wv, bv);

    attn_mma_kernel<<<dim3(NSEQ / 64, NB * NH), 256,
                      ATTN_SMEM_FLOATS * (int)sizeof(float)>>>();

    gemm_out_mma<<<dim3(CONC / 128, MTOT / 128), 256>>>(W0, b0, out);
}

// round 7
// speedup vs baseline: 28.1454x; 1.9219x over previous
#include <cuda_runtime.h>
#include <cuda_fp16.h>
#include <math.h>
#include <cstdint>

// Problem constants
#define EMB   768
#define DHEAD 256
#define NB    8
#define NSEQ  2048
#define NH    3
#define MTOT  (NB * NSEQ)          // 16384
#define CONC  (NH * DHEAD)         // 768
#define SCALE 0.0625f              // 1/sqrt(256)
#define NHEADS (NB * NH)           // 24

// Scratch (half everywhere except stats). __align__(16): these are accessed
// with 16-byte vector ld/st; __device__ half arrays only guarantee 2B
// alignment otherwise, and a misaligned LDG.128 is a hardware trap.
__device__ __align__(16) __half g_xh [MTOT * EMB];             // x as half
__device__ __align__(16) __half g_Wth[9 * DHEAD * EMB];        // [mat*3+h][n][k]
__device__ __align__(16) __half g_W0th[CONC * CONC];           // [n][k]
__device__ __align__(16) __half g_Qh [NHEADS * NSEQ * DHEAD];  // [head][n][d]
__device__ __align__(16) __half g_Kh [NHEADS * NSEQ * DHEAD];
__device__ __align__(16) __half g_Vh [NHEADS * NSEQ * DHEAD];
__device__ __align__(16) __half g_Vth[NHEADS * DHEAD * NSEQ];  // [head][d][n]
__device__ __align__(16) __half g_Oh [MTOT * CONC];            // attn out, concat

// ---------------------------------------------------------------------------
// fp16 mma m16n8k16, f32 accumulate
// ---------------------------------------------------------------------------
__device__ __forceinline__ void mma_f16(float* d, const unsigned* a, const unsigned* b) {
    asm volatile(
        "mma.sync.aligned.m16n8k16.row.col.f32.f16.f16.f32 "
        "{%0,%1,%2,%3},{%4,%5,%6,%7},{%8,%9},{%0,%1,%2,%3};"
        : "+f"(d[0]), "+f"(d[1]), "+f"(d[2]), "+f"(d[3])
        : "r"(a[0]), "r"(a[1]), "r"(a[2]), "r"(a[3]), "r"(b[0]), "r"(b[1]));
}
__device__ __forceinline__ unsigned ldh2(const __half* p) {
    return *(const unsigned*)p;
}

// ---------------------------------------------------------------------------
// Prep kernels
// ---------------------------------------------------------------------------
__global__ void conv_x_kernel(const float* __restrict__ in, int n) {
    int i = (blockIdx.x * blockDim.x + threadIdx.x) * 8;
    if (i >= n) return;
    float4 a = *(const float4*)&in[i];
    float4 b = *(const float4*)&in[i + 4];
    *(half2*)&g_xh[i + 0] = __floats2half2_rn(a.x, a.y);
    *(half2*)&g_xh[i + 2] = __floats2half2_rn(a.z, a.w);
    *(half2*)&g_xh[i + 4] = __floats2half2_rn(b.x, b.y);
    *(half2*)&g_xh[i + 6] = __floats2half2_rn(b.z, b.w);
}

// in [bz][K][N] float -> out [bz][N][K] half
__global__ void transpose_conv_w(const float* __restrict__ in, __half* __restrict__ out,
                                 int K, int N)
{
    __shared__ float tile[32][33];
    const int bz = blockIdx.z;
    in  += (size_t)bz * K * N;
    out += (size_t)bz * K * N;
    const int k0 = blockIdx.x * 32, n0 = blockIdx.y * 32;
    const int tx = threadIdx.x, ty = threadIdx.y;
    #pragma unroll
    for (int i = 0; i < 32; i += 8)
        tile[ty + i][tx] = in[(size_t)(k0 + ty + i) * N + n0 + tx];
    __syncthreads();
    #pragma unroll
    for (int i = 0; i < 32; i += 8)
        out[(size_t)(n0 + ty + i) * K + k0 + tx] = __float2half(tile[tx][ty + i]);
}

// per-head transpose: g_Vh [head][n][d] -> g_Vth [head][d][n]
__global__ void vtrans_kernel() {
    __shared__ __half tile[32][33];
    const int head = blockIdx.z;
    const __half* in = g_Vh + (size_t)head * NSEQ * DHEAD;
    __half* out = g_Vth + (size_t)head * DHEAD * NSEQ;
    const int n0 = blockIdx.x * 32, d0 = blockIdx.y * 32;
    const int tx = threadIdx.x, ty = threadIdx.y;
    #pragma unroll
    for (int i = 0; i < 32; i += 8)
        tile[ty + i][tx] = in[(size_t)(n0 + ty + i) * DHEAD + d0 + tx];
    __syncthreads();
    #pragma unroll
    for (int i = 0; i < 32; i += 8)
        out[(size_t)(d0 + ty + i) * NSEQ + n0 + tx] = tile[tx][ty + i];
}

// ---------------------------------------------------------------------------
// Shared fp16 GEMM mainloop: C(128x128) += A(128xK,half) * Bt(128xK,half)^T
// BK=32. 8 warps 2(m) x 4(n), warp tile 64x32 via m16n8k16.
// As/Bs stride 40 halfs (half2-index stride 20 == 4 mod 32: conflict-free).
// ---------------------------------------------------------------------------
#define GST 40

__device__ __forceinline__ void gemm_mainloop_h(
    const __half* __restrict__ A, int lda, int m0,
    const __half* __restrict__ Bt, int ldb, int n0,
    int Kdim, float acc[4][4][4],
    __half As[128][GST], __half Bs[128][GST])
{
    const int tid = threadIdx.x;
    const int lane = tid & 31;
    const int wid = tid >> 5;
    const int wm = wid & 1;
    const int wn = wid >> 1;
    const int gr = lane >> 2;        // fragment row
    const int gt = lane & 3;         // fragment k-pair

    for (int k0 = 0; k0 < Kdim; k0 += 32) {
        #pragma unroll
        for (int i = 0; i < 2; i++) {           // A: 128 rows x 32 halfs (4 int4/row)
            int f = tid + i * 256;
            int r = f >> 2, ch = f & 3;
            *(int4*)&As[r][ch * 8] = *(const int4*)&A[(size_t)(m0 + r) * lda + k0 + ch * 8];
        }
        #pragma unroll
        for (int i = 0; i < 2; i++) {           // B: 128 n-rows x 32 halfs
            int f = tid + i * 256;
            int r = f >> 2, ch = f & 3;
            *(int4*)&Bs[r][ch * 8] = *(const int4*)&Bt[(size_t)(n0 + r) * ldb + k0 + ch * 8];
        }
        __syncthreads();

        #pragma unroll
        for (int ks = 0; ks < 2; ks++) {
            const int kb = ks * 16;
            unsigned af[4][4], bf[4][2];
            #pragma unroll
            for (int mt = 0; mt < 4; mt++) {
                int r = wm * 64 + mt * 16 + gr;
                af[mt][0] = ldh2(&As[r][kb + 2 * gt]);
                af[mt][1] = ldh2(&As[r + 8][kb + 2 * gt]);
                af[mt][2] = ldh2(&As[r][kb + 8 + 2 * gt]);
                af[mt][3] = ldh2(&As[r + 8][kb + 8 + 2 * gt]);
            }
            #pragma unroll
            for (int nt = 0; nt < 4; nt++) {
                int nr = wn * 32 + nt * 8 + gr;
                bf[nt][0] = ldh2(&Bs[nr][kb + 2 * gt]);
                bf[nt][1] = ldh2(&Bs[nr][kb + 8 + 2 * gt]);
            }
            #pragma unroll
            for (int mt = 0; mt < 4; mt++)
                #pragma unroll
                for (int nt = 0; nt < 4; nt++)
                    mma_f16(acc[mt][nt], af[mt], bf[nt]);
        }
        __syncthreads();
    }
}

// ---------------------------------------------------------------------------
// GEMM 1: QKV projections -> half Q/K/V. z = mat*3 + h
// ---------------------------------------------------------------------------
__global__ __launch_bounds__(256) void gemm_qkv_h(
    const float* __restrict__ bq, const float* __restrict__ bk,
    const float* __restrict__ bv)
{
    __shared__ __half As[128][GST];
    __shared__ __half Bs[128][GST];

    const int z = blockIdx.z, mat = z / 3, h = z % 3;
    const float* bias;
    __half* out;
    if (mat == 0)      { bias = bq; out = g_Qh; }
    else if (mat == 1) { bias = bk; out = g_Kh; }
    else               { bias = bv; out = g_Vh; }
    bias += h * DHEAD;

    const __half* Bt = g_Wth + (size_t)z * DHEAD * EMB;
    const int m0 = blockIdx.y * 128;
    const int n0 = blockIdx.x * 128;

    float acc[4][4][4] = {};
    gemm_mainloop_h(g_xh, EMB, m0, Bt, EMB, n0, EMB, acc, As, Bs);

    const int lane = threadIdx.x & 31, wid = threadIdx.x >> 5;
    const int wm = wid & 1, wn = wid >> 1;
    #pragma unroll
    for (int mt = 0; mt < 4; mt++) {
        int gr0 = m0 + wm * 64 + mt * 16 + (lane >> 2);
        int gr1 = gr0 + 8;
        int bi0 = gr0 >> 11, n0r = gr0 & 2047;
        int bi1 = gr1 >> 11, n1r = gr1 & 2047;
        __half* p0 = out + ((size_t)(bi0 * 3 + h) * NSEQ + n0r) * DHEAD;
        __half* p1 = out + ((size_t)(bi1 * 3 + h) * NSEQ + n1r) * DHEAD;
        #pragma unroll
        for (int nt = 0; nt < 4; nt++) {
            int c = n0 + wn * 32 + nt * 8 + ((lane & 3) << 1);
            float b0v = bias[c], b1v = bias[c + 1];
            *(half2*)&p0[c] = __floats2half2_rn(acc[mt][nt][0] + b0v, acc[mt][nt][1] + b1v);
            *(half2*)&p1[c] = __floats2half2_rn(acc[mt][nt][2] + b0v, acc[mt][nt][3] + b1v);
        }
    }
}

// ---------------------------------------------------------------------------
// GEMM 2: out[16384,768] = g_Oh @ W0 + b0 (fp32 out)
// ---------------------------------------------------------------------------
__global__ __launch_bounds__(256) void gemm_out_h(
    const float* __restrict__ b0, float* __restrict__ outp)
{
    __shared__ __half As[128][GST];
    __shared__ __half Bs[128][GST];

    const int m0 = blockIdx.y * 128;
    const int n0 = blockIdx.x * 128;

    float acc[4][4][4] = {};
    gemm_mainloop_h(g_Oh, CONC, m0, g_W0th, CONC, n0, CONC, acc, As, Bs);

    const int lane = threadIdx.x & 31, wid = threadIdx.x >> 5;
    const int wm = wid & 1, wn = wid >> 1;
    #pragma unroll
    for (int mt = 0; mt < 4; mt++) {
        int gr0 = m0 + wm * 64 + mt * 16 + (lane >> 2);
        int gr1 = gr0 + 8;
        #pragma unroll
        for (int nt = 0; nt < 4; nt++) {
            int c = n0 + wn * 32 + nt * 8 + ((lane & 3) << 1);
            float bb0 = b0[c], bb1 = b0[c + 1];
            *(float2*)&outp[(size_t)gr0 * CONC + c] =
                make_float2(acc[mt][nt][0] + bb0, acc[mt][nt][1] + bb1);
            *(float2*)&outp[(size_t)gr1 * CONC + c] =
                make_float2(acc[mt][nt][2] + bb0, acc[mt][nt][3] + bb1);
        }
    }
}

// ---------------------------------------------------------------------------
// Flash attention, fp16 mma. CTA = 64 queries x one head. 8 warps:
// wm = wid&3 (16-query group), wn = wid>>2 (key half for S / D half for PV).
// smem (halfs): Qs,Ks stride 264 (h2-stride 132 == 4 mod 32), Vt/Ps stride 72
// (h2-stride 36 == 4 mod 32) -> all fragment gathers conflict-free.
// ---------------------------------------------------------------------------
#define QKST 264
#define VTST 72
#define PST  72
#define ATTN_SMEM_BYTES ((64 * QKST * 2 + 64 * QKST * 2 + 256 * VTST * 2 + 64 * PST * 2) + 3 * 64 * 4)

__global__ __launch_bounds__(256) void attn_h_kernel()
{
    extern __shared__ __align__(16) char smc[];
    __half (*Qs)[QKST] = (__half(*)[QKST])smc;
    __half (*Ks)[QKST] = (__half(*)[QKST])(smc + 64 * QKST * 2);
    __half (*Vt)[VTST] = (__half(*)[VTST])(smc + 2 * 64 * QKST * 2);
    __half (*Ps)[PST]  = (__half(*)[PST]) (smc + 2 * 64 * QKST * 2 + 256 * VTST * 2);
    float* rowM = (float*)(smc + 2 * 64 * QKST * 2 + 256 * VTST * 2 + 64 * PST * 2);
    float* rowL = rowM + 64;
    float* rowC = rowL + 64;

    const int t = threadIdx.x, lane = t & 31, wid = t >> 5;
    const int wm = wid & 3;
    const int wn = wid >> 2;
    const int gr = lane >> 2;
    const int gt = lane & 3;
    const int head = blockIdx.y;
    const int b = head / 3, h = head % 3;
    const int q0 = blockIdx.x * 64;
    const size_t hb  = (size_t)head * NSEQ * DHEAD;
    const size_t hbt = (size_t)head * DHEAD * NSEQ;

    // Stage Q (64 x 256 halfs; 32 int4-chunks per row)
    {
        const __half* Qg = g_Qh + hb + (size_t)q0 * DHEAD;
        #pragma unroll
        for (int i = 0; i < 8; i++) {
            int f = t + i * 256;
            int r = f >> 5, ch = f & 31;
            *(int4*)&Qs[r][ch * 8] = *(const int4*)&Qg[(size_t)r * DHEAD + ch * 8];
        }
    }
    if (t < 64) { rowM[t] = -INFINITY; rowL[t] = 0.f; }

    float o[16][4];
    #pragma unroll
    for (int i = 0; i < 16; i++)
        { o[i][0] = 0.f; o[i][1] = 0.f; o[i][2] = 0.f; o[i][3] = 0.f; }

    __syncthreads();

    for (int kt = 0; kt < NSEQ / 64; kt++) {
        // Stage K tile (64x256) and Vt tile (256 d x 64 keys)
        {
            const __half* Kg = g_Kh + hb + (size_t)kt * 64 * DHEAD;
            const __half* Vg = g_Vth + hbt + (size_t)kt * 64;
            #pragma unroll
            for (int i = 0; i < 8; i++) {
                int f = t + i * 256;
                int r = f >> 5, ch = f & 31;
                *(int4*)&Ks[r][ch * 8] = *(const int4*)&Kg[(size_t)r * DHEAD + ch * 8];
            }
            #pragma unroll
            for (int i = 0; i < 8; i++) {
                int f = t + i * 256;
                int d = f >> 3, ch = f & 7;
                *(int4*)&Vt[d][ch * 8] = *(const int4*)&Vg[(size_t)d * NSEQ + ch * 8];
            }
        }
        __syncthreads();

        // S = Q K^T : warp computes 16 rows (wm) x 32 keys (wn), k=256
        float s[4][4] = {};
        #pragma unroll
        for (int ks = 0; ks < 16; ks++) {
            const int kb = ks * 16;
            unsigned af[4];
            int r = wm * 16 + gr;
            af[0] = ldh2(&Qs[r][kb + 2 * gt]);
            af[1] = ldh2(&Qs[r + 8][kb + 2 * gt]);
            af[2] = ldh2(&Qs[r][kb + 8 + 2 * gt]);
            af[3] = ldh2(&Qs[r + 8][kb + 8 + 2 * gt]);
            #pragma unroll
            for (int nt = 0; nt < 4; nt++) {
                int key = wn * 32 + nt * 8 + gr;
                unsigned bf[2] = { ldh2(&Ks[key][kb + 2 * gt]),
                                   ldh2(&Ks[key][kb + 8 + 2 * gt]) };
                mma_f16(s[nt], af, bf);
            }
        }

        // Write scaled S to Ps (half)
        {
            int r = wm * 16 + gr;
            #pragma unroll
            for (int nt = 0; nt < 4; nt++) {
                int c = wn * 32 + nt * 8 + 2 * gt;
                *(half2*)&Ps[r][c]     = __floats2half2_rn(s[nt][0] * SCALE, s[nt][1] * SCALE);
                *(half2*)&Ps[r + 8][c] = __floats2half2_rn(s[nt][2] * SCALE, s[nt][3] * SCALE);
            }
        }
        __syncthreads();

        // Online softmax row pass: 4 threads per row, 16 cols each
        {
            int r = t >> 2, sub = t & 3;
            __half* pr = &Ps[r][sub * 16];
            float v[16];
            #pragma unroll
            for (int j = 0; j < 8; j++) {
                float2 f2 = __half22float2(*(half2*)&pr[2 * j]);
                v[2 * j] = f2.x; v[2 * j + 1] = f2.y;
            }
            float tm = -INFINITY;
            #pragma unroll
            for (int j = 0; j < 16; j++) tm = fmaxf(tm, v[j]);
            tm = fmaxf(tm, __shfl_xor_sync(0xffffffffu, tm, 1));
            tm = fmaxf(tm, __shfl_xor_sync(0xffffffffu, tm, 2));
            float mprev = rowM[r];
            float newm = fmaxf(mprev, tm);
            float corr = __expf(mprev - newm);
            float sum = 0.f;
            #pragma unroll
            for (int j = 0; j < 16; j++) {
                v[j] = __expf(v[j] - newm);
                sum += v[j];
            }
            #pragma unroll
            for (int j = 0; j < 8; j++)
                *(half2*)&pr[2 * j] = __floats2half2_rn(v[2 * j], v[2 * j + 1]);
            sum += __shfl_xor_sync(0xffffffffu, sum, 1);
            sum += __shfl_xor_sync(0xffffffffu, sum, 2);
            if (sub == 0) {
                rowM[r] = newm;
                rowL[r] = rowL[r] * corr + sum;
                rowC[r] = corr;
            }
        }
        __syncthreads();

        // Rescale O
        {
            float c0 = rowC[wm * 16 + gr];
            float c1 = rowC[wm * 16 + gr + 8];
            #pragma unroll
            for (int nt = 0; nt < 16; nt++) {
                o[nt][0] *= c0; o[nt][1] *= c0;
                o[nt][2] *= c1; o[nt][3] *= c1;
            }
        }

        // O += P V : warp computes 16 rows x 128 D-cols (wn half), k=64
        #pragma unroll
        for (int ks = 0; ks < 4; ks++) {
            const int kb = ks * 16;
            unsigned af[4];
            int r = wm * 16 + gr;
            af[0] = ldh2(&Ps[r][kb + 2 * gt]);
            af[1] = ldh2(&Ps[r + 8][kb + 2 * gt]);
            af[2] = ldh2(&Ps[r][kb + 8 + 2 * gt]);
            af[3] = ldh2(&Ps[r + 8][kb + 8 + 2 * gt]);
            #pragma unroll
            for (int nt = 0; nt < 16; nt++) {
                int d = wn * 128 + nt * 8 + gr;
                unsigned bf[2] = { ldh2(&Vt[d][kb + 2 * gt]),
                                   ldh2(&Vt[d][kb + 8 + 2 * gt]) };
                mma_f16(o[nt], af, bf);
            }
        }
        __syncthreads();
    }

    // Epilogue: normalize + store half to concat layout [b, n, h*256 + d]
    {
        int r0 = wm * 16 + gr, r1 = r0 + 8;
        float inv0 = 1.f / rowL[r0];
        float inv1 = 1.f / rowL[r1];
        size_t obase = ((size_t)b * NSEQ + q0) * CONC + h * DHEAD;
        #pragma unroll
        for (int nt = 0; nt < 16; nt++) {
            int c = wn * 128 + nt * 8 + 2 * gt;
            *(half2*)&g_Oh[obase + (size_t)r0 * CONC + c] =
                __floats2half2_rn(o[nt][0] * inv0, o[nt][1] * inv0);
            *(half2*)&g_Oh[obase + (size_t)r1 * CONC + c] =
                __floats2half2_rn(o[nt][2] * inv1, o[nt][3] * inv1);
        }
    }
}

// ---------------------------------------------------------------------------
extern "C" void kernel_launch(void* const* d_in, const int* in_sizes, int n_in,
                              void* d_out, int out_size)
{
    const float* x  = (const float*)d_in[0];
    const float* Wq = (const float*)d_in[1];
    const float* bq = (const float*)d_in[2];
    const float* Wk = (const float*)d_in[3];
    const float* bk = (const float*)d_in[4];
    const float* Wv = (const float*)d_in[5];
    const float* bv = (const float*)d_in[6];
    const float* W0 = (const float*)d_in[7];
    const float* b0 = (const float*)d_in[8];
    float* out = (float*)d_out;

    static bool attr_done = false;
    if (!attr_done) {
        cudaFuncSetAttribute(attn_h_kernel,
                             cudaFuncAttributeMaxDynamicSharedMemorySize,
                             ATTN_SMEM_BYTES);
        attr_done = true;
    }

    // Prep: x -> half; weights -> transposed half
    conv_x_kernel<<<(MTOT * EMB / 8 + 255) / 256, 256>>>(x, MTOT * EMB);
    {
        __half* wt = nullptr;  cudaGetSymbolAddress((void**)&wt, g_Wth);
        __half* w0t = nullptr; cudaGetSymbolAddress((void**)&w0t, g_W0th);
        dim3 tb(32, 8);
        transpose_conv_w<<<dim3(EMB / 32, DHEAD / 32, 3), tb>>>(Wq, wt + (size_t)0 * 3 * DHEAD * EMB, EMB, DHEAD);
        transpose_conv_w<<<dim3(EMB / 32, DHEAD / 32, 3), tb>>>(Wk, wt + (size_t)1 * 3 * DHEAD * EMB, EMB, DHEAD);
        transpose_conv_w<<<dim3(EMB / 32, DHEAD / 32, 3), tb>>>(Wv, wt + (size_t)2 * 3 * DHEAD * EMB, EMB, DHEAD);
        transpose_conv_w<<<dim3(CONC / 32, CONC / 32, 1), tb>>>(W0, w0t, CONC, CONC);
    }

    // QKV projections
    gemm_qkv_h<<<dim3(DHEAD / 128, MTOT / 128, 9), 256>>>(bq, bk, bv);

    // V transpose per head
    vtrans_kernel<<<dim3(NSEQ / 32, DHEAD / 32, NHEADS), dim3(32, 8)>>>();

    // Attention
    attn_h_kernel<<<dim3(NSEQ / 64, NHEADS), 256, ATTN_SMEM_BYTES>>>();

    // Output projection
    gemm_out_h<<<dim3(CONC / 128, MTOT / 128), 256>>>(b0, out);
}

// round 10
// speedup vs baseline: 30.2930x; 1.0763x over previous
#include <cuda_runtime.h>
#include <cuda_fp16.h>
#include <math.h>
#include <cstdint>

// Problem constants
#define EMB   768
#define DHEAD 256
#define NB    8
#define NSEQ  2048
#define NH    3
#define MTOT  (NB * NSEQ)          // 16384
#define CONC  (NH * DHEAD)         // 768
#define SCALE 0.0625f              // 1/sqrt(256)
#define NHEADS (NB * NH)           // 24

// Scratch. __align__(16): accessed with 16-byte vector ld/st.
__device__ __align__(16) __half g_xh [MTOT * EMB];
__device__ __align__(16) __half g_Wth[9 * DHEAD * EMB];        // [mat*3+h][n][k]
__device__ __align__(16) __half g_W0th[CONC * CONC];           // [n][k]
__device__ __align__(16) __half g_Qh [NHEADS * NSEQ * DHEAD];  // [head][n][d]
__device__ __align__(16) __half g_Kh [NHEADS * NSEQ * DHEAD];
__device__ __align__(16) __half g_Vh [NHEADS * NSEQ * DHEAD];
__device__ __align__(16) __half g_Vth[NHEADS * DHEAD * NSEQ];  // [head][d][n]
__device__ __align__(16) __half g_Oh [MTOT * CONC];            // attn out, concat

// ---------------------------------------------------------------------------
// fp16 mma m16n8k16, f32 accumulate
// ---------------------------------------------------------------------------
__device__ __forceinline__ void mma_f16(float* d, const unsigned* a, const unsigned* b) {
    asm volatile(
        "mma.sync.aligned.m16n8k16.row.col.f32.f16.f16.f32 "
        "{%0,%1,%2,%3},{%4,%5,%6,%7},{%8,%9},{%0,%1,%2,%3};"
        : "+f"(d[0]), "+f"(d[1]), "+f"(d[2]), "+f"(d[3])
        : "r"(a[0]), "r"(a[1]), "r"(a[2]), "r"(a[3]), "r"(b[0]), "r"(b[1]));
}
__device__ __forceinline__ unsigned ldh2(const __half* p) {
    return *(const unsigned*)p;
}
__device__ __forceinline__ uint32_t smem_u32(const void* p) {
    uint32_t a;
    asm("{ .reg .u64 t; cvta.to.shared.u64 t, %1; cvt.u32.u64 %0, t; }" : "=r"(a) : "l"(p));
    return a;
}
__device__ __forceinline__ void cpa16(uint32_t dst, const void* src) {
    asm volatile("cp.async.cg.shared.global [%0], [%1], 16;" :: "r"(dst), "l"(src));
}
#define CPA_COMMIT() asm volatile("cp.async.commit_group;" ::: "memory")
#define CPA_WAIT0()  asm volatile("cp.async.wait_group 0;" ::: "memory")

// ---------------------------------------------------------------------------
// Prep kernels (unchanged from R7, known good)
// ---------------------------------------------------------------------------
__global__ void conv_x_kernel(const float* __restrict__ in, int n) {
    int i = (blockIdx.x * blockDim.x + threadIdx.x) * 8;
    if (i >= n) return;
    float4 a = *(const float4*)&in[i];
    float4 b = *(const float4*)&in[i + 4];
    *(half2*)&g_xh[i + 0] = __floats2half2_rn(a.x, a.y);
    *(half2*)&g_xh[i + 2] = __floats2half2_rn(a.z, a.w);
    *(half2*)&g_xh[i + 4] = __floats2half2_rn(b.x, b.y);
    *(half2*)&g_xh[i + 6] = __floats2half2_rn(b.z, b.w);
}

// in [bz][K][N] float -> out [bz][N][K] half
__global__ void transpose_conv_w(const float* __restrict__ in, __half* __restrict__ out,
                                 int K, int N)
{
    __shared__ float tile[32][33];
    const int bz = blockIdx.z;
    in  += (size_t)bz * K * N;
    out += (size_t)bz * K * N;
    const int k0 = blockIdx.x * 32, n0 = blockIdx.y * 32;
    const int tx = threadIdx.x, ty = threadIdx.y;
    #pragma unroll
    for (int i = 0; i < 32; i += 8)
        tile[ty + i][tx] = in[(size_t)(k0 + ty + i) * N + n0 + tx];
    __syncthreads();
    #pragma unroll
    for (int i = 0; i < 32; i += 8)
        out[(size_t)(n0 + ty + i) * K + k0 + tx] = __float2half(tile[tx][ty + i]);
}

// per-head transpose: g_Vh [head][n][d] -> g_Vth [head][d][n]
__global__ void vtrans_kernel() {
    __shared__ __half tile[32][33];
    const int head = blockIdx.z;
    const __half* in = g_Vh + (size_t)head * NSEQ * DHEAD;
    __half* out = g_Vth + (size_t)head * DHEAD * NSEQ;
    const int n0 = blockIdx.x * 32, d0 = blockIdx.y * 32;
    const int tx = threadIdx.x, ty = threadIdx.y;
    #pragma unroll
    for (int i = 0; i < 32; i += 8)
        tile[ty + i][tx] = in[(size_t)(n0 + ty + i) * DHEAD + d0 + tx];
    __syncthreads();
    #pragma unroll
    for (int i = 0; i < 32; i += 8)
        out[(size_t)(d0 + ty + i) * NSEQ + n0 + tx] = tile[tx][ty + i];
}

// ---------------------------------------------------------------------------
// Shared fp16 GEMM mainloop (unchanged from R7, known good)
// ---------------------------------------------------------------------------
#define GST 40

__device__ __forceinline__ void gemm_mainloop_h(
    const __half* __restrict__ A, int lda, int m0,
    const __half* __restrict__ Bt, int ldb, int n0,
    int Kdim, float acc[4][4][4],
    __half As[128][GST], __half Bs[128][GST])
{
    const int tid = threadIdx.x;
    const int lane = tid & 31;
    const int wid = tid >> 5;
    const int wm = wid & 1;
    const int wn = wid >> 1;
    const int gr = lane >> 2;
    const int gt = lane & 3;

    for (int k0 = 0; k0 < Kdim; k0 += 32) {
        #pragma unroll
        for (int i = 0; i < 2; i++) {
            int f = tid + i * 256;
            int r = f >> 2, ch = f & 3;
            *(int4*)&As[r][ch * 8] = *(const int4*)&A[(size_t)(m0 + r) * lda + k0 + ch * 8];
        }
        #pragma unroll
        for (int i = 0; i < 2; i++) {
            int f = tid + i * 256;
            int r = f >> 2, ch = f & 3;
            *(int4*)&Bs[r][ch * 8] = *(const int4*)&Bt[(size_t)(n0 + r) * ldb + k0 + ch * 8];
        }
        __syncthreads();

        #pragma unroll
        for (int ks = 0; ks < 2; ks++) {
            const int kb = ks * 16;
            unsigned af[4][4], bf[4][2];
            #pragma unroll
            for (int mt = 0; mt < 4; mt++) {
                int r = wm * 64 + mt * 16 + gr;
                af[mt][0] = ldh2(&As[r][kb + 2 * gt]);
                af[mt][1] = ldh2(&As[r + 8][kb + 2 * gt]);
                af[mt][2] = ldh2(&As[r][kb + 8 + 2 * gt]);
                af[mt][3] = ldh2(&As[r + 8][kb + 8 + 2 * gt]);
            }
            #pragma unroll
            for (int nt = 0; nt < 4; nt++) {
                int nr = wn * 32 + nt * 8 + gr;
                bf[nt][0] = ldh2(&Bs[nr][kb + 2 * gt]);
                bf[nt][1] = ldh2(&Bs[nr][kb + 8 + 2 * gt]);
            }
            #pragma unroll
            for (int mt = 0; mt < 4; mt++)
                #pragma unroll
                for (int nt = 0; nt < 4; nt++)
                    mma_f16(acc[mt][nt], af[mt], bf[nt]);
        }
        __syncthreads();
    }
}

// ---------------------------------------------------------------------------
// GEMM 1: QKV projections -> half Q/K/V. z = mat*3 + h
// ---------------------------------------------------------------------------
__global__ __launch_bounds__(256) void gemm_qkv_h(
    const float* __restrict__ bq, const float* __restrict__ bk,
    const float* __restrict__ bv)
{
    __shared__ __half As[128][GST];
    __shared__ __half Bs[128][GST];

    const int z = blockIdx.z, mat = z / 3, h = z % 3;
    const float* bias;
    __half* out;
    if (mat == 0)      { bias = bq; out = g_Qh; }
    else if (mat == 1) { bias = bk; out = g_Kh; }
    else               { bias = bv; out = g_Vh; }
    bias += h * DHEAD;

    const __half* Bt = g_Wth + (size_t)z * DHEAD * EMB;
    const int m0 = blockIdx.y * 128;
    const int n0 = blockIdx.x * 128;

    float acc[4][4][4] = {};
    gemm_mainloop_h(g_xh, EMB, m0, Bt, EMB, n0, EMB, acc, As, Bs);

    const int lane = threadIdx.x & 31, wid = threadIdx.x >> 5;
    const int wm = wid & 1, wn = wid >> 1;
    #pragma unroll
    for (int mt = 0; mt < 4; mt++) {
        int gr0 = m0 + wm * 64 + mt * 16 + (lane >> 2);
        int gr1 = gr0 + 8;
        int bi0 = gr0 >> 11, n0r = gr0 & 2047;
        int bi1 = gr1 >> 11, n1r = gr1 & 2047;
        __half* p0 = out + ((size_t)(bi0 * 3 + h) * NSEQ + n0r) * DHEAD;
        __half* p1 = out + ((size_t)(bi1 * 3 + h) * NSEQ + n1r) * DHEAD;
        #pragma unroll
        for (int nt = 0; nt < 4; nt++) {
            int c = n0 + wn * 32 + nt * 8 + ((lane & 3) << 1);
            float b0v = bias[c], b1v = bias[c + 1];
            *(half2*)&p0[c] = __floats2half2_rn(acc[mt][nt][0] + b0v, acc[mt][nt][1] + b1v);
            *(half2*)&p1[c] = __floats2half2_rn(acc[mt][nt][2] + b0v, acc[mt][nt][3] + b1v);
        }
    }
}

// ---------------------------------------------------------------------------
// GEMM 2: out[16384,768] = g_Oh @ W0 + b0 (fp32 out)
// ---------------------------------------------------------------------------
__global__ __launch_bounds__(256) void gemm_out_h(
    const float* __restrict__ b0, float* __restrict__ outp)
{
    __shared__ __half As[128][GST];
    __shared__ __half Bs[128][GST];

    const int m0 = blockIdx.y * 128;
    const int n0 = blockIdx.x * 128;

    float acc[4][4][4] = {};
    gemm_mainloop_h(g_Oh, CONC, m0, g_W0th, CONC, n0, CONC, acc, As, Bs);

    const int lane = threadIdx.x & 31, wid = threadIdx.x >> 5;
    const int wm = wid & 1, wn = wid >> 1;
    #pragma unroll
    for (int mt = 0; mt < 4; mt++) {
        int gr0 = m0 + wm * 64 + mt * 16 + (lane >> 2);
        int gr1 = gr0 + 8;
        #pragma unroll
        for (int nt = 0; nt < 4; nt++) {
            int c = n0 + wn * 32 + nt * 8 + ((lane & 3) << 1);
            float bb0 = b0[c], bb1 = b0[c + 1];
            *(float2*)&outp[(size_t)gr0 * CONC + c] =
                make_float2(acc[mt][nt][0] + bb0, acc[mt][nt][1] + bb1);
            *(float2*)&outp[(size_t)gr1 * CONC + c] =
                make_float2(acc[mt][nt][2] + bb0, acc[mt][nt][3] + bb1);
        }
    }
}

// ---------------------------------------------------------------------------
// Flash attention (R7 geometry + cp.async pipeline bisect):
// Bq=64 queries/CTA, 256 threads, 8 warps. wm=wid&3 (16-row group),
// wn=wid>>2 (key half for S / D half for PV). gr=lane>>2, gt=lane&3.
// NEW vs R7: Ks refilled via cp.async after the post-S barrier; Vt
// double-buffered via cp.async; waits at loop end overlap loads with
// softmax + PV compute. Fragment layouts identical to R7 (known good).
// smem: Qs[64][264] 33792B, Ks[64][264] 33792B, Vt[2][256][72] 73728B,
// Ps[64][72] 9216B, stats 768B -> 151296 B.
// ---------------------------------------------------------------------------
#define QKST 264
#define VTST 72
#define PST  72
#define KS_OFF (64 * QKST * 2)                        // 33792
#define VT_OFF (KS_OFF + 64 * QKST * 2)               // 67584
#define VT_BYTES (256 * VTST * 2)                     // 36864
#define PS_OFF (VT_OFF + 2 * VT_BYTES)                // 141312
#define ST_OFF (PS_OFF + 64 * PST * 2)                // 150528
#define ATTN_SMEM_BYTES (ST_OFF + 3 * 64 * 4)         // 151296
#define NT (NSEQ / 64)                                // 32

__global__ __launch_bounds__(256) void attn_h_kernel()
{
    extern __shared__ __align__(16) char smc[];
    __half (*Qs)[QKST] = (__half(*)[QKST])smc;
    __half (*Ks)[QKST] = (__half(*)[QKST])(smc + KS_OFF);
    __half (*Ps)[PST]  = (__half(*)[PST]) (smc + PS_OFF);
    float* rowM = (float*)(smc + ST_OFF);
    float* rowL = rowM + 64;
    float* rowC = rowL + 64;
    const uint32_t sbase = smem_u32(smc);

    const int t = threadIdx.x, lane = t & 31, wid = t >> 5;
    const int wm = wid & 3;     // 16-row group (4 groups x 16 = 64)
    const int wn = wid >> 2;    // 0..1
    const int gr = lane >> 2;
    const int gt = lane & 3;
    const int head = blockIdx.y;
    const int b = head / 3, h = head % 3;
    const int q0 = blockIdx.x * 64;
    const size_t hb  = (size_t)head * NSEQ * DHEAD;
    const size_t hbt = (size_t)head * DHEAD * NSEQ;

    // Stage Q (64 x 256 halfs = 2048 int4 chunks; 8 per thread)
    {
        const __half* Qg = g_Qh + hb + (size_t)q0 * DHEAD;
        #pragma unroll
        for (int i = 0; i < 8; i++) {
            int f = t + i * 256;
            int r = f >> 5, ch = f & 31;
            *(int4*)&Qs[r][ch * 8] = *(const int4*)&Qg[(size_t)r * DHEAD + ch * 8];
        }
    }
    // Issue cp.async for K[0] and Vt[0] -> buf 0
    {
        const __half* Kg = g_Kh + hb;
        const __half* Vg = g_Vth + hbt;
        #pragma unroll
        for (int i = 0; i < 8; i++) {
            int f = t + i * 256;
            int r = f >> 5, ch = f & 31;
            cpa16(sbase + KS_OFF + (uint32_t)(r * QKST + ch * 8) * 2,
                  Kg + (size_t)r * DHEAD + ch * 8);
        }
        #pragma unroll
        for (int i = 0; i < 8; i++) {
            int f = t + i * 256;
            int d = f >> 3, ch = f & 7;
            cpa16(sbase + VT_OFF + (uint32_t)(d * VTST + ch * 8) * 2,
                  Vg + (size_t)d * NSEQ + ch * 8);
        }
        CPA_COMMIT();
    }
    if (t < 64) { rowM[t] = -INFINITY; rowL[t] = 0.f; }

    float o[16][4];
    #pragma unroll
    for (int i = 0; i < 16; i++)
        { o[i][0] = 0.f; o[i][1] = 0.f; o[i][2] = 0.f; o[i][3] = 0.f; }

    CPA_WAIT0();
    __syncthreads();

    int buf = 0;
    for (int kt = 0; kt < NT; kt++) {
        const __half (*Vt)[VTST] = (const __half(*)[VTST])(smc + VT_OFF + buf * VT_BYTES);

        // S = Q K^T : warp computes 16 rows (wm) x 32 keys (wn), k=256
        float s[4][4] = {};
        #pragma unroll
        for (int ks = 0; ks < 16; ks++) {
            const int kb = ks * 16;
            unsigned af[4];
            int r = wm * 16 + gr;
            af[0] = ldh2(&Qs[r][kb + 2 * gt]);
            af[1] = ldh2(&Qs[r + 8][kb + 2 * gt]);
            af[2] = ldh2(&Qs[r][kb + 8 + 2 * gt]);
            af[3] = ldh2(&Qs[r + 8][kb + 8 + 2 * gt]);
            #pragma unroll
            for (int nt = 0; nt < 4; nt++) {
                int key = wn * 32 + nt * 8 + gr;
                unsigned bf[2] = { ldh2(&Ks[key][kb + 2 * gt]),
                                   ldh2(&Ks[key][kb + 8 + 2 * gt]) };
                mma_f16(s[nt], af, bf);
            }
        }

        // Write scaled S to Ps (half)
        {
            int r = wm * 16 + gr;
            #pragma unroll
            for (int nt = 0; nt < 4; nt++) {
                int c = wn * 32 + nt * 8 + 2 * gt;
                *(half2*)&Ps[r][c]     = __floats2half2_rn(s[nt][0] * SCALE, s[nt][1] * SCALE);
                *(half2*)&Ps[r + 8][c] = __floats2half2_rn(s[nt][2] * SCALE, s[nt][3] * SCALE);
            }
        }
        __syncthreads();   // Ps visible; all Ks reads done

        // Prefetch next K tile (into Ks) and next Vt tile (into buf^1)
        if (kt + 1 < NT) {
            const __half* Kg = g_Kh + hb + (size_t)(kt + 1) * 64 * DHEAD;
            const __half* Vg = g_Vth + hbt + (size_t)(kt + 1) * 64;
            const uint32_t vdst = sbase + VT_OFF + (uint32_t)(buf ^ 1) * VT_BYTES;
            #pragma unroll
            for (int i = 0; i < 8; i++) {
                int f = t + i * 256;
                int r = f >> 5, ch = f & 31;
                cpa16(sbase + KS_OFF + (uint32_t)(r * QKST + ch * 8) * 2,
                      Kg + (size_t)r * DHEAD + ch * 8);
            }
            #pragma unroll
            for (int i = 0; i < 8; i++) {
                int f = t + i * 256;
                int d = f >> 3, ch = f & 7;
                cpa16(vdst + (uint32_t)(d * VTST + ch * 8) * 2,
                      Vg + (size_t)d * NSEQ + ch * 8);
            }
            CPA_COMMIT();
        }

        // Online softmax row pass: 4 threads per row, 16 cols each
        {
            int r = t >> 2, sub = t & 3;
            __half* pr = &Ps[r][sub * 16];
            float v[16];
            #pragma unroll
            for (int j = 0; j < 8; j++) {
                float2 f2 = __half22float2(*(half2*)&pr[2 * j]);
                v[2 * j] = f2.x; v[2 * j + 1] = f2.y;
            }
            float tm = -INFINITY;
            #pragma unroll
            for (int j = 0; j < 16; j++) tm = fmaxf(tm, v[j]);
            tm = fmaxf(tm, __shfl_xor_sync(0xffffffffu, tm, 1));
            tm = fmaxf(tm, __shfl_xor_sync(0xffffffffu, tm, 2));
            float mprev = rowM[r];
            float newm = fmaxf(mprev, tm);
            float corr = __expf(mprev - newm);
            float sum = 0.f;
            #pragma unroll
            for (int j = 0; j < 16; j++) {
                v[j] = __expf(v[j] - newm);
                sum += v[j];
            }
            #pragma unroll
            for (int j = 0; j < 8; j++)
                *(half2*)&pr[2 * j] = __floats2half2_rn(v[2 * j], v[2 * j + 1]);
            sum += __shfl_xor_sync(0xffffffffu, sum, 1);
            sum += __shfl_xor_sync(0xffffffffu, sum, 2);
            if (sub == 0) {
                rowM[r] = newm;
                rowL[r] = rowL[r] * corr + sum;
                rowC[r] = corr;
            }
        }
        __syncthreads();

        // Rescale O
        {
            float c0 = rowC[wm * 16 + gr];
            float c1 = rowC[wm * 16 + gr + 8];
            #pragma unroll
            for (int nt = 0; nt < 16; nt++) {
                o[nt][0] *= c0; o[nt][1] *= c0;
                o[nt][2] *= c1; o[nt][3] *= c1;
            }
        }

        // O += P V : warp computes 16 rows x 128 D-cols (wn half), k=64
        #pragma unroll
        for (int ks = 0; ks < 4; ks++) {
            const int kb = ks * 16;
            unsigned af[4];
            int r = wm * 16 + gr;
            af[0] = ldh2(&Ps[r][kb + 2 * gt]);
            af[1] = ldh2(&Ps[r + 8][kb + 2 * gt]);
            af[2] = ldh2(&Ps[r][kb + 8 + 2 * gt]);
            af[3] = ldh2(&Ps[r + 8][kb + 8 + 2 * gt]);
            #pragma unroll
            for (int nt = 0; nt < 16; nt++) {
                int d = wn * 128 + nt * 8 + gr;
                unsigned bf[2] = { ldh2(&Vt[d][kb + 2 * gt]),
                                   ldh2(&Vt[d][kb + 8 + 2 * gt]) };
                mma_f16(o[nt], af, bf);
            }
        }
        buf ^= 1;
        CPA_WAIT0();        // next K/Vt tiles landed (this thread's copies)
        __syncthreads();    // cross-thread visibility + Ps/Ks reuse safety
    }

    // Epilogue: normalize + store half to concat layout [b, n, h*256 + d]
    {
        int r0 = wm * 16 + gr, r1 = r0 + 8;
        float inv0 = 1.f / rowL[r0];
        float inv1 = 1.f / rowL[r1];
        size_t obase = ((size_t)b * NSEQ + q0) * CONC + h * DHEAD;
        #pragma unroll
        for (int nt = 0; nt < 16; nt++) {
            int c = wn * 128 + nt * 8 + 2 * gt;
            *(half2*)&g_Oh[obase + (size_t)r0 * CONC + c] =
                __floats2half2_rn(o[nt][0] * inv0, o[nt][1] * inv0);
            *(half2*)&g_Oh[obase + (size_t)r1 * CONC + c] =
                __floats2half2_rn(o[nt][2] * inv1, o[nt][3] * inv1);
        }
    }
}

// ---------------------------------------------------------------------------
extern "C" void kernel_launch(void* const* d_in, const int* in_sizes, int n_in,
                              void* d_out, int out_size)
{
    const float* x  = (const float*)d_in[0];
    const float* Wq = (const float*)d_in[1];
    const float* bq = (const float*)d_in[2];
    const float* Wk = (const float*)d_in[3];
    const float* bk = (const float*)d_in[4];
    const float* Wv = (const float*)d_in[5];
    const float* bv = (const float*)d_in[6];
    const float* W0 = (const float*)d_in[7];
    const float* b0 = (const float*)d_in[8];
    float* out = (float*)d_out;

    static bool attr_done = false;
    if (!attr_done) {
        cudaFuncSetAttribute(attn_h_kernel,
                             cudaFuncAttributeMaxDynamicSharedMemorySize,
                             ATTN_SMEM_BYTES);
        attr_done = true;
    }

    // Prep: x -> half; weights -> transposed half
    conv_x_kernel<<<(MTOT * EMB / 8 + 255) / 256, 256>>>(x, MTOT * EMB);
    {
        __half* wt = nullptr;  cudaGetSymbolAddress((void**)&wt, g_Wth);
        __half* w0t = nullptr; cudaGetSymbolAddress((void**)&w0t, g_W0th);
        dim3 tb(32, 8);
        transpose_conv_w<<<dim3(EMB / 32, DHEAD / 32, 3), tb>>>(Wq, wt + (size_t)0 * 3 * DHEAD * EMB, EMB, DHEAD);
        transpose_conv_w<<<dim3(EMB / 32, DHEAD / 32, 3), tb>>>(Wk, wt + (size_t)1 * 3 * DHEAD * EMB, EMB, DHEAD);
        transpose_conv_w<<<dim3(EMB / 32, DHEAD / 32, 3), tb>>>(Wv, wt + (size_t)2 * 3 * DHEAD * EMB, EMB, DHEAD);
        transpose_conv_w<<<dim3(CONC / 32, CONC / 32, 1), tb>>>(W0, w0t, CONC, CONC);
    }

    // QKV projections
    gemm_qkv_h<<<dim3(DHEAD / 128, MTOT / 128, 9), 256>>>(bq, bk, bv);

    // V transpose per head
    vtrans_kernel<<<dim3(NSEQ / 32, DHEAD / 32, NHEADS), dim3(32, 8)>>>();

    // Attention (64 queries per CTA, 256 threads — R7 geometry + cp.async)
    attn_h_kernel<<<dim3(NSEQ / 64, NHEADS), 256, ATTN_SMEM_BYTES>>>();

    // Output projection
    gemm_out_h<<<dim3(CONC / 128, MTOT / 128), 256>>>(b0, out);
}